// round 12
// baseline (speedup 1.0000x reference)
#include <cuda_runtime.h>
#include <cuda_fp16.h>

#define NBINS 64
#define NT 128              // threads per block (hist kernel)
#define BPI 12              // blocks per image -> NBLK 576 = 4*144: one wave
#define NIMG 48             // 2 tensors * 8 batch * 3 channels
#define IMG_PIX 65536       // 256*256
#define IMG_F4 16384        // float4 elements per image
#define WIN 3               // half-width (validated: rel_err ~1.1e-4)
#define NPAIR 36            // bin-pairs: bins -4..67 (guards absorb edges)
#define NBLK (NIMG * BPI)   // 576

// zero at load; finalize re-zeroes after reading each call (graph-replay safe)
__device__ float g_hist[NIMG * NBINS];

// ============================================================================
// Half2 pair-packed accumulation: the fp32 version sits at the smem crossbar
// byte roofline (128 B/cyc/SM, 14 warp-accesses/px). A 7-bin window spans
// EXACTLY 4 aligned bin-pairs for either j0 parity, so half2 packing cuts
// crossbar accesses to 8/px. fp16 rounding is random (not systematic): it
// averages out across 1536 columns and again across the 1536 |cum-diff|
// terms of the loss -> negligible vs the WIN=3 systematic 1e-4.
// FULL-unrolled 64-iter reduce = register ballast keeping ptxas out of its
// 32-40-reg spill regime (R5-R7, R9). DO NOT fuse the finalize here
// (R3/R7/R9: fusion always perturbed allocation and doubled the main loop).
// ============================================================================
__global__ __launch_bounds__(NT) void hist_kernel(const float* __restrict__ pred,
                                                  const float* __restrict__ tgt) {
    // per-thread private pair columns: sh2[pair*NT + tid] (18,432 B)
    // bank = tid % 32 for every pair row -> conflict-free
    __shared__ __half2 sh2[NPAIR * NT];
    __shared__ float psx[64], psy[64];

    const int tid = threadIdx.x;
    const int img = blockIdx.x / BPI;
    const int blk = blockIdx.x % BPI;

    const float* src = (img < 24) ? pred : tgt;
    const int cimg   = (img < 24) ? img : img - 24;
    const float4* base = (const float4*)(src + (size_t)cimg * IMG_PIX);

    const int f0 = (blk    ) * IMG_F4 / BPI;
    const int f1 = (blk + 1) * IMG_F4 / BPI;

    for (int i = tid; i < NPAIR * NT; i += NT)
        sh2[i] = __floats2half2_rn(0.0f, 0.0f);
    __syncthreads();

    // Gaussian soft-assignment, geometric recurrence:
    // w_k = w0 * prod(s),  s: e^(+-C*d0)*v, then *= v^2 each step
    const float A   = 2048.0f;          // 1/(2*bin_width^2)
    const float DLT = 1.0f / 63.0f;
    const float C   = 4096.0f / 63.0f;  // 2*A*DLT
    const float v   = __expf(-A * DLT * DLT);
    const float v2  = v * v;

    for (int i = f0 + tid; i < f1; i += NT) {
        float4 xv = base[i];
        #pragma unroll
        for (int c = 0; c < 4; c++) {
            float x = (c == 0) ? xv.x : (c == 1) ? xv.y : (c == 2) ? xv.z : xv.w;
            // inputs uniform in [0,1): rn(x*63) already in [0,63]
            int j0 = __float2int_rn(x * 63.0f);
            float d0 = fmaf(-(float)j0, DLT, x);      // x - j0/63
            float w0 = __expf(-A * d0 * d0);
            float eu = __expf( C * d0);
            float ed = __expf(-C * d0);

            float w, s, wp1, wp2, wp3, wm1, wm2, wm3;
            w = w0; s = eu * v;
            w *= s; wp1 = w; s *= v2;
            w *= s; wp2 = w; s *= v2;
            w *= s; wp3 = w;
            w = w0; s = ed * v;
            w *= s; wm1 = w; s *= v2;
            w *= s; wm2 = w; s *= v2;
            w *= s; wm3 = w;

            // window bins j0-3..j0+3 span pairs p..p+3, p = (j0+1)>>1.
            // pair q holds bins (2q-4, 2q-3). parity select packs weights.
            bool e = (j0 & 1);
            __half2 q0 = __floats2half2_rn(e ? wm3 : 0.0f, e ? wm2 : wm3);
            __half2 q1 = __floats2half2_rn(e ? wm1 : wm2,  e ? w0  : wm1);
            __half2 q2 = __floats2half2_rn(e ? wp1 : w0,   e ? wp2 : wp1);
            __half2 q3 = __floats2half2_rn(e ? wp3 : wp2,  e ? 0.0f : wp3);

            __half2* hp = sh2 + ((j0 + 1) >> 1) * NT + tid;
            hp[0]      = __hadd2(hp[0],      q0);
            hp[1 * NT] = __hadd2(hp[1 * NT], q1);
            hp[2 * NT] = __hadd2(hp[2 * NT], q2);
            hp[3 * NT] = __hadd2(hp[3 * NT], q3);
        }
    }
    __syncthreads();

    // Reduce: 64 tasks (32 interior pairs x 2 column-halves); task t sums 64
    // half2 columns in fp32. Guards (pairs 0,1,34,35) discarded. FULL unroll
    // on purpose (register ballast). Lane-staggered -> conflict-free.
    if (tid < 64) {
        int pair  = 2 + (tid >> 1);
        int cbase = (tid & 1) * 64;
        const __half2* row = sh2 + pair * NT;
        float ax = 0.0f, ay = 0.0f;
        #pragma unroll
        for (int i = 0; i < 64; i++) {
            float2 f = __half22float2(row[cbase + ((i + tid) & 63)]);
            ax += f.x; ay += f.y;
        }
        psx[tid] = ax; psy[tid] = ay;
    }
    __syncthreads();
    if (tid < NBINS) {
        // bin t lives in pair 2+(t>>1) = tasks (t&~1, (t&~1)+1), slot t&1
        int idx = tid & ~1;
        float val = (tid & 1) ? (psy[idx] + psy[idx + 1])
                              : (psx[idx] + psx[idx + 1]);
        // spread-address atomics across 48*64 words: ~REDG rate, cheap.
        atomicAdd(&g_hist[img * NBINS + tid], val);
    }
}

// ============================================================================
// Finalize: 1 block x 768 threads = 24 warps, one (pred,target) channel pair
// per warp. PDL-launched: scheduled while hist runs, gated by
// cudaGridDependencySynchronize(). Re-zeroes g_hist for the next replay.
// ============================================================================
#define FNT 768

__device__ __forceinline__ float wscan(float x, int lane) {
    #pragma unroll
    for (int o = 1; o < 32; o <<= 1) {
        float n = __shfl_up_sync(0xffffffffu, x, o);
        if (lane >= o) x += n;
    }
    return x;
}

__global__ __launch_bounds__(FNT) void finalize_kernel(float* __restrict__ out) {
    // Wait for the preceding hist_kernel (PDL gate).
    cudaGridDependencySynchronize();

    __shared__ float accs[24];
    const int tid  = threadIdx.x;
    const int warp = tid >> 5;      // 0..23 = channel pair
    const int lane = tid & 31;

    const float* hp = g_hist + warp * NBINS;
    const float* ht = g_hist + (24 + warp) * NBINS;
    float pl = hp[lane], ph = hp[lane + 32];
    float tl = ht[lane], th = ht[lane + 32];

    float pls = wscan(pl, lane);
    float phs = wscan(ph, lane) + __shfl_sync(0xffffffffu, pls, 31);
    float tls = wscan(tl, lane);
    float ths = wscan(th, lane) + __shfl_sync(0xffffffffu, tls, 31);

    float rp = 1.0f / (__shfl_sync(0xffffffffu, phs, 31) + 1e-7f);
    float rt = 1.0f / (__shfl_sync(0xffffffffu, ths, 31) + 1e-7f);

    float acc = fabsf(pls * rp - tls * rt) + fabsf(phs * rp - ths * rt);
    #pragma unroll
    for (int o = 16; o > 0; o >>= 1)
        acc += __shfl_xor_sync(0xffffffffu, acc, o);
    if (lane == 0) accs[warp] = acc;
    __syncthreads();

    if (tid == 0) {
        float s = 0.0f;
        #pragma unroll
        for (int c = 0; c < 24; c++) s += accs[c];
        out[0] = s * (1.0f / 1536.0f);   // mean over (8,3,64)
    }

    // re-zero accumulators for the next replay (deterministic end state)
    for (int p = tid; p < NIMG * NBINS; p += FNT) g_hist[p] = 0.0f;
}

extern "C" void kernel_launch(void* const* d_in, const int* in_sizes, int n_in,
                              void* d_out, int out_size) {
    const float* pred = (const float*)d_in[0];
    const float* tgt  = (const float*)d_in[1];
    float* out        = (float*)d_out;

    cudaFuncSetAttribute(hist_kernel,
                         cudaFuncAttributePreferredSharedMemoryCarveout,
                         cudaSharedmemCarveoutMaxShared);

    hist_kernel<<<NBLK, NT>>>(pred, tgt);

    // PDL launch: finalize block is scheduled/prefetched while hist runs.
    cudaLaunchConfig_t cfg = {};
    cfg.gridDim  = dim3(1, 1, 1);
    cfg.blockDim = dim3(FNT, 1, 1);
    cfg.dynamicSmemBytes = 0;
    cudaLaunchAttribute attrs[1];
    attrs[0].id = cudaLaunchAttributeProgrammaticStreamSerialization;
    attrs[0].val.programmaticStreamSerializationAllowed = 1;
    cfg.attrs = attrs;
    cfg.numAttrs = 1;
    cudaLaunchKernelEx(&cfg, finalize_kernel, out);
}

// round 13
// speedup vs baseline: 1.1404x; 1.1404x over previous
#include <cuda_runtime.h>

#define NBINS 64
#define NT 128              // threads per block (hist kernel)
#define BPI 12              // blocks per image -> NBLK 576 = 4*144: one wave
#define NIMG 48             // 2 tensors * 8 batch * 3 channels
#define IMG_PIX 65536       // 256*256
#define IMG_F4 16384        // float4 elements per image
#define WIN 3               // half-width (validated: rel_err ~1.05e-4)
#define NROW (NBINS + 2*WIN)  // 70 rows: bins -3..66 (guards absorb edges)
#define NBLK (NIMG * BPI)   // 576

// zero at load; finalize re-zeroes after reading each call (graph-replay safe)
__device__ float g_hist[NIMG * NBINS];

// ============================================================================
// Hist kernel: byte-identical main loop to R11 (15.1us, fp32, the proven
// fast compilation regime; the R12 half2 rewrite left the regime and
// regressed). FULL-unrolled 64-LDS reduce = register ballast keeping ptxas
// out of its 32-40-reg spill regime (R5-R7, R9, R12). DO NOT fuse the
// finalize here (R3/R7/R9) and DO NOT restructure the main loop.
// R13's only change: tid==0 fires cudaTriggerProgrammaticLaunchCompletion()
// at block end so the PDL-launched finalize is dispatched during hist's tail
// instead of after grid completion (R11 had no trigger -> implicit trigger
// at kernel end -> dispatch latency fully serial).
// ============================================================================
__global__ __launch_bounds__(NT) void hist_kernel(const float* __restrict__ pred,
                                                  const float* __restrict__ tgt) {
    // per-thread private histogram columns: sh[row*NT + tid]
    // bank = tid % 32 for every row -> conflict-free for any per-lane bin
    __shared__ float sh[NROW * NT];      // 35,840 B
    __shared__ float psum[2 * NBINS];

    const int tid = threadIdx.x;
    const int img = blockIdx.x / BPI;
    const int blk = blockIdx.x % BPI;

    const float* src = (img < 24) ? pred : tgt;
    const int cimg   = (img < 24) ? img : img - 24;
    const float4* base = (const float4*)(src + (size_t)cimg * IMG_PIX);

    const int f0 = (blk    ) * IMG_F4 / BPI;
    const int f1 = (blk + 1) * IMG_F4 / BPI;

    for (int i = tid; i < NROW * NT; i += NT) sh[i] = 0.0f;
    __syncthreads();

    // Gaussian soft-assignment, geometric recurrence:
    // w_k = w0 * prod(s),  s: e^(+-C*d0)*v, then *= v^2 each step
    const float A   = 2048.0f;          // 1/(2*bin_width^2)
    const float DLT = 1.0f / 63.0f;
    const float C   = 4096.0f / 63.0f;  // 2*A*DLT
    const float v   = __expf(-A * DLT * DLT);
    const float v2  = v * v;

    for (int i = f0 + tid; i < f1; i += NT) {
        float4 xv = base[i];
        #pragma unroll
        for (int c = 0; c < 4; c++) {
            float x = (c == 0) ? xv.x : (c == 1) ? xv.y : (c == 2) ? xv.z : xv.w;
            // inputs uniform in [0,1): rn(x*63) already in [0,63]
            int j0 = __float2int_rn(x * 63.0f);
            float d0 = fmaf(-(float)j0, DLT, x);      // x - j0/63
            float w0 = __expf(-A * d0 * d0);
            float eu = __expf( C * d0);
            float ed = __expf(-C * d0);

            float* h = sh + (j0 + WIN) * NT + tid;    // immediate-offset RMWs
            h[0] += w0;

            float w = w0, s = eu * v;
            #pragma unroll
            for (int k = 1; k <= WIN; k++) {
                w *= s; s *= v2;
                h[k * NT] += w;
            }
            w = w0; s = ed * v;
            #pragma unroll
            for (int k = 1; k <= WIN; k++) {
                w *= s; s *= v2;
                h[-k * NT] += w;
            }
        }
    }
    __syncthreads();

    // Reduce 128 thread-columns. thread t: bin = t&63, half = t>>6 sums 64
    // cols. Lane-staggered start keeps banks distinct. FULL unroll on purpose
    // (register ballast; see header comment).
    {
        int bin  = tid & 63;
        int part = tid >> 6;
        int cbase = part * 64;
        const float* row = sh + (bin + WIN) * NT;
        float acc = 0.0f;
        #pragma unroll
        for (int i = 0; i < 64; i++) {
            acc += row[cbase + ((i + tid) & 63)];
        }
        psum[part * 64 + bin] = acc;
    }
    __syncthreads();
    if (tid < NBINS) {
        // spread-address atomics across 48*64 words: ~REDG rate, cheap.
        atomicAdd(&g_hist[img * NBINS + tid], psum[tid] + psum[64 + tid]);
    }

    // Release the PDL-dependent finalize launch early: once every CTA has
    // triggered, the finalize block is dispatched and parks in
    // cudaGridDependencySynchronize() (which still waits for this grid's
    // memory to be visible -> correctness unchanged).
    if (tid == 0) cudaTriggerProgrammaticLaunchCompletion();
}

// ============================================================================
// Finalize: 1 block x 768 threads = 24 warps, one (pred,target) channel pair
// per warp. PDL-launched: dispatched during hist's tail (trigger above),
// gated by cudaGridDependencySynchronize(). Re-zeroes g_hist for next replay.
// ============================================================================
#define FNT 768

__device__ __forceinline__ float wscan(float x, int lane) {
    #pragma unroll
    for (int o = 1; o < 32; o <<= 1) {
        float n = __shfl_up_sync(0xffffffffu, x, o);
        if (lane >= o) x += n;
    }
    return x;
}

__global__ __launch_bounds__(FNT) void finalize_kernel(float* __restrict__ out) {
    // Wait until the preceding hist grid's memory operations are visible.
    cudaGridDependencySynchronize();

    __shared__ float accs[24];
    const int tid  = threadIdx.x;
    const int warp = tid >> 5;      // 0..23 = channel pair
    const int lane = tid & 31;

    const float* hp = g_hist + warp * NBINS;
    const float* ht = g_hist + (24 + warp) * NBINS;
    float pl = hp[lane], ph = hp[lane + 32];
    float tl = ht[lane], th = ht[lane + 32];

    float pls = wscan(pl, lane);
    float phs = wscan(ph, lane) + __shfl_sync(0xffffffffu, pls, 31);
    float tls = wscan(tl, lane);
    float ths = wscan(th, lane) + __shfl_sync(0xffffffffu, tls, 31);

    float rp = 1.0f / (__shfl_sync(0xffffffffu, phs, 31) + 1e-7f);
    float rt = 1.0f / (__shfl_sync(0xffffffffu, ths, 31) + 1e-7f);

    float acc = fabsf(pls * rp - tls * rt) + fabsf(phs * rp - ths * rt);
    #pragma unroll
    for (int o = 16; o > 0; o >>= 1)
        acc += __shfl_xor_sync(0xffffffffu, acc, o);
    if (lane == 0) accs[warp] = acc;
    __syncthreads();

    if (tid == 0) {
        float s = 0.0f;
        #pragma unroll
        for (int c = 0; c < 24; c++) s += accs[c];
        out[0] = s * (1.0f / 1536.0f);   // mean over (8,3,64)
    }

    // re-zero accumulators for the next replay (deterministic end state)
    for (int p = tid; p < NIMG * NBINS; p += FNT) g_hist[p] = 0.0f;
}

extern "C" void kernel_launch(void* const* d_in, const int* in_sizes, int n_in,
                              void* d_out, int out_size) {
    const float* pred = (const float*)d_in[0];
    const float* tgt  = (const float*)d_in[1];
    float* out        = (float*)d_out;

    cudaFuncSetAttribute(hist_kernel,
                         cudaFuncAttributePreferredSharedMemoryCarveout,
                         cudaSharedmemCarveoutMaxShared);

    hist_kernel<<<NBLK, NT>>>(pred, tgt);

    // PDL launch: finalize is dispatched when hist's CTAs trigger completion,
    // overlapping the grid-1 dispatch latency with hist's tail.
    cudaLaunchConfig_t cfg = {};
    cfg.gridDim  = dim3(1, 1, 1);
    cfg.blockDim = dim3(FNT, 1, 1);
    cfg.dynamicSmemBytes = 0;
    cudaLaunchAttribute attrs[1];
    attrs[0].id = cudaLaunchAttributeProgrammaticStreamSerialization;
    attrs[0].val.programmaticStreamSerializationAllowed = 1;
    cfg.attrs = attrs;
    cfg.numAttrs = 1;
    cudaLaunchKernelEx(&cfg, finalize_kernel, out);
}